// round 4
// baseline (speedup 1.0000x reference)
#include <cuda_runtime.h>
#include <cuda_bf16.h>

// LengthRegulator: B=32, L=512, D=384, T_MAX=4096, EXPAND_SCALE=1.0, PAD=0
// Outputs: out (B,T,D) float32  [+ exp_dur (B,L) appended if out_size allows]

#define BB 32
#define LL 512
#define DD 384
#define TT 4096
#define D4 (DD / 4)          // 96 float4 per row
#define ROWS_PER_BLK 8       // one warp per output row

__device__ int g_cum[BB][LL];   // inclusive cumsum of expanded durations
__device__ int g_dur64;         // 1 if duration buffer is int64, else int32
__device__ int g_mask32;        // 1 if padding_mask buffer is int32, else uint8/bool

// ---------------------------------------------------------------------------
// Kernel A: sniff dtypes from the bytes themselves (deterministic per data).
//  - duration: values in [0,8). If stored int64 (LE), every odd 32-bit word
//    is 0. For real int32 data, 1024 random words all-zero has prob 8^-1024.
//  - mask: if stored int32 (0/1), all bytes at index i%4!=0 are 0. If stored
//    as bool (1 byte), those bytes are random 0/1 -> some byte is 1 whp.
// All probed indices stay inside the SMALLER possible buffer, so no OOB.
// ---------------------------------------------------------------------------
__global__ void detect_kernel(const int* dur32_view, const unsigned char* mask8_view) {
    __shared__ int any_odd;      // nonzero odd word in duration
    __shared__ int any_pad;      // nonzero non-lsb byte in mask
    if (threadIdx.x == 0) { any_odd = 0; any_pad = 0; }
    __syncthreads();
    // duration: probe odd words 1,3,...,2047  (8 KB < min(64KB,128KB))
    for (int i = threadIdx.x; i < 1024; i += blockDim.x) {
        if (dur32_view[2 * i + 1] != 0) any_odd = 1;
    }
    // mask: probe bytes in [0,16384) with i%4 != 0 (16 KB = min buffer size)
    for (int i = threadIdx.x; i < 16384; i += blockDim.x) {
        if ((i & 3) != 0 && mask8_view[i] != 0) any_pad = 1;
    }
    __syncthreads();
    if (threadIdx.x == 0) {
        g_dur64  = (any_odd == 0) ? 1 : 0;  // all odd words zero -> int64
        g_mask32 = (any_pad == 0) ? 1 : 0;  // all pad bytes zero -> int32
    }
}

// ---------------------------------------------------------------------------
// Kernel B: per-batch inclusive scan of exp_dur (== duration, scale=1.0),
// store cum to g_cum, optionally write exp_dur (as float) to d_out tail.
// One block per batch, 512 threads.
// ---------------------------------------------------------------------------
__global__ void scan_kernel(const void* dur_raw, float* expdur_out, int write_expdur) {
    __shared__ int s[LL];
    const int b = blockIdx.x;
    const int t = threadIdx.x;

    int v;
    if (g_dur64) v = (int)((const long long*)dur_raw)[b * LL + t];
    else         v = ((const int*)dur_raw)[b * LL + t];
    // EXPAND_SCALE = 1.0 -> round(1.0 * d) == d for small non-negative ints

    s[t] = v;
    __syncthreads();
    // Hillis-Steele inclusive scan over 512 elements
    #pragma unroll
    for (int off = 1; off < LL; off <<= 1) {
        int x = (t >= off) ? s[t - off] : 0;
        __syncthreads();
        s[t] += x;
        __syncthreads();
    }
    g_cum[b][t] = s[t];
    if (write_expdur) expdur_out[b * LL + t] = (float)v;
}

// ---------------------------------------------------------------------------
// Kernel C: expansion. Block handles 8 consecutive output rows of one batch
// (T=4096 divisible by 8, so a block never straddles batches).
// Warp w -> one row. Binary search in shared cum (9 steps), then stream the
// 1536-byte row as float4 (96 vecs, 3 iters of 32 lanes).
// ---------------------------------------------------------------------------
__global__ void __launch_bounds__(256) expand_kernel(
    const float4* __restrict__ seq,
    const void*   __restrict__ mask_raw,
    float4*       __restrict__ out)
{
    __shared__ int s_cum[LL];
    const int rowBase = blockIdx.x * ROWS_PER_BLK;      // global row index (b*T + j)
    const int b = rowBase >> 12;                        // / TT
    const int tid = threadIdx.x;

    for (int i = tid; i < LL; i += 256) s_cum[i] = g_cum[b][i];
    __syncthreads();

    const int w    = tid >> 5;
    const int lane = tid & 31;
    const int j    = (rowBase & (TT - 1)) + w;          // row within [0,T)
    const int total = s_cum[LL - 1];

    float4* orow = out + (size_t)(rowBase + w) * D4;
    const float4 z = make_float4(0.f, 0.f, 0.f, 0.f);

    if (j >= total) {
        #pragma unroll
        for (int c = lane; c < D4; c += 32) orow[c] = z;
        return;
    }

    // searchsorted right: count of cum entries <= j
    int lo = 0, hi = LL;
    #pragma unroll 9
    while (lo < hi) {
        int mid = (lo + hi) >> 1;
        if (s_cum[mid] <= j) lo = mid + 1; else hi = mid;
    }
    const int idx = lo;                                 // guaranteed <= LL-1 here

    int padded;
    if (g_mask32) padded = ((const int*)mask_raw)[b * LL + idx];
    else          padded = ((const unsigned char*)mask_raw)[b * LL + idx];

    if (padded) {
        #pragma unroll
        for (int c = lane; c < D4; c += 32) orow[c] = z;
    } else {
        const float4* srow = seq + (size_t)(b * LL + idx) * D4;
        #pragma unroll
        for (int c = lane; c < D4; c += 32) orow[c] = srow[c];
    }
}

// ---------------------------------------------------------------------------
extern "C" void kernel_launch(void* const* d_in, const int* in_sizes, int n_in,
                              void* d_out, int out_size) {
    const float* seq  = (const float*)d_in[0];
    const void*  dur  = d_in[1];
    const void*  mask = d_in[2];
    float* out = (float*)d_out;

    const long long main_elems = (long long)BB * TT * DD;   // 50,331,648
    const int write_expdur = ((long long)out_size >= main_elems + (long long)BB * LL) ? 1 : 0;

    detect_kernel<<<1, 256>>>((const int*)dur, (const unsigned char*)mask);
    scan_kernel<<<BB, LL>>>(dur, out + main_elems, write_expdur);
    expand_kernel<<<(BB * TT) / ROWS_PER_BLK, 256>>>(
        (const float4*)seq, mask, (float4*)out);
}

// round 7
// speedup vs baseline: 2.1407x; 2.1407x over previous
#include <cuda_runtime.h>
#include <cuda_bf16.h>

// LengthRegulator: B=32, L=512, D=384, T_MAX=4096, EXPAND_SCALE=1.0, PAD=0
// Outputs: out (B,T,D) float32  [+ exp_dur (B,L) appended if out_size allows]

#define BB 32
#define LL 512
#define DD 384
#define TT 4096
#define D4 (DD / 4)          // 96 float4 per row
#define ROWS_PER_BLK 8       // one warp per output row

__device__ int g_cum[BB][LL];   // inclusive cumsum of expanded durations
__device__ int g_mask32;        // 1 if padding_mask buffer is int32, else uint8/bool

// ---------------------------------------------------------------------------
// Kernel B: per-batch inclusive scan of exp_dur (== duration, scale=1.0).
// FUSED dtype detection (replaces the 35us detect kernel):
//  - duration: values in [0,8). If stored int64 (LE), every odd 32-bit word
//    of the buffer is 0. Probe the first 8KB (safe: min buffer is 64KB) with
//    one int4 load per thread. P(false int64 | int32 data) = 8^-1024.
//  - mask: if stored int32 (0/1), all bytes at i%4!=0 are 0; if bool, those
//    bytes are ~random 0/1. Probe first 8KB (min buffer 16KB) as int4 and
//    test (word & 0xFFFFFF00). P(false int32 | bool data) = 2^-6144.
// Every block computes the same verdict from the same bytes -> deterministic;
// the racy g_mask32 writes all store the identical value.
// One block per batch, 512 threads.
// ---------------------------------------------------------------------------
__global__ void __launch_bounds__(LL) scan_kernel(
    const void* __restrict__ dur_raw,
    const void* __restrict__ mask_raw,
    float* expdur_out, int write_expdur)
{
    __shared__ int s[LL];
    __shared__ int f_odd;    // nonzero odd word in duration probe
    __shared__ int f_pad;    // nonzero high byte in mask probe
    const int b = blockIdx.x;
    const int t = threadIdx.x;

    if (t == 0) { f_odd = 0; f_pad = 0; }
    __syncthreads();

    // --- dtype probes: one int4 each, first 8KB of each buffer ---
    {
        int4 dp = ((const int4*)dur_raw)[t];           // words 4t..4t+3
        if (dp.y | dp.w) f_odd = 1;                    // odd words nonzero -> int32
        int4 mp = ((const int4*)mask_raw)[t];
        if ((dp.x & 0) | ((mp.x | mp.y | mp.z | mp.w) & 0xFFFFFF00)) f_pad = 1;
    }
    __syncthreads();

    const int dur64  = (f_odd == 0);
    const int mask32 = (f_pad == 0);
    if (t == 0) g_mask32 = mask32;

    int v;
    if (dur64) v = (int)((const long long*)dur_raw)[b * LL + t];
    else       v = ((const int*)dur_raw)[b * LL + t];
    // EXPAND_SCALE = 1.0 -> round(1.0 * d) == d for small non-negative ints

    s[t] = v;
    __syncthreads();
    // Hillis-Steele inclusive scan over 512 elements
    #pragma unroll
    for (int off = 1; off < LL; off <<= 1) {
        int x = (t >= off) ? s[t - off] : 0;
        __syncthreads();
        s[t] += x;
        __syncthreads();
    }
    g_cum[b][t] = s[t];
    if (write_expdur) expdur_out[b * LL + t] = (float)v;
}

// ---------------------------------------------------------------------------
// Kernel C: expansion. Block handles 8 consecutive output rows of one batch
// (T=4096 divisible by 8, so a block never straddles batches).
// Warp w -> one row. Binary search in shared cum (9 steps), then stream the
// 1536-byte row as float4 (96 vecs, 3 iters of 32 lanes). Output stores use
// __stcs (evict-first): the 192MB store stream must not evict the 24MB
// L2-resident seq working set.
// ---------------------------------------------------------------------------
__global__ void __launch_bounds__(256) expand_kernel(
    const float4* __restrict__ seq,
    const void*   __restrict__ mask_raw,
    float4*       __restrict__ out)
{
    __shared__ int s_cum[LL];
    const int rowBase = blockIdx.x * ROWS_PER_BLK;      // global row index (b*T + j)
    const int b = rowBase >> 12;                        // / TT
    const int tid = threadIdx.x;

    for (int i = tid; i < LL; i += 256) s_cum[i] = g_cum[b][i];
    __syncthreads();

    const int w    = tid >> 5;
    const int lane = tid & 31;
    const int j    = (rowBase & (TT - 1)) + w;          // row within [0,T)
    const int total = s_cum[LL - 1];

    float4* orow = out + (size_t)(rowBase + w) * D4;
    const float4 z = make_float4(0.f, 0.f, 0.f, 0.f);

    if (j >= total) {
        #pragma unroll
        for (int c = lane; c < D4; c += 32) __stcs(&orow[c], z);
        return;
    }

    // searchsorted right: count of cum entries <= j
    int lo = 0, hi = LL;
    #pragma unroll 9
    while (lo < hi) {
        int mid = (lo + hi) >> 1;
        if (s_cum[mid] <= j) lo = mid + 1; else hi = mid;
    }
    const int idx = lo;                                 // guaranteed <= LL-1 here

    int padded;
    if (g_mask32) padded = ((const int*)mask_raw)[b * LL + idx];
    else          padded = ((const unsigned char*)mask_raw)[b * LL + idx];

    if (padded) {
        #pragma unroll
        for (int c = lane; c < D4; c += 32) __stcs(&orow[c], z);
    } else {
        const float4* srow = seq + (size_t)(b * LL + idx) * D4;
        #pragma unroll
        for (int c = lane; c < D4; c += 32) __stcs(&orow[c], __ldg(&srow[c]));
    }
}

// ---------------------------------------------------------------------------
extern "C" void kernel_launch(void* const* d_in, const int* in_sizes, int n_in,
                              void* d_out, int out_size) {
    const float* seq  = (const float*)d_in[0];
    const void*  dur  = d_in[1];
    const void*  mask = d_in[2];
    float* out = (float*)d_out;

    const long long main_elems = (long long)BB * TT * DD;   // 50,331,648
    const int write_expdur = ((long long)out_size >= main_elems + (long long)BB * LL) ? 1 : 0;

    scan_kernel<<<BB, LL>>>(dur, mask, out + main_elems, write_expdur);
    expand_kernel<<<(BB * TT) / ROWS_PER_BLK, 256>>>(
        (const float4*)seq, mask, (float4*)out);
}